// round 11
// baseline (speedup 1.0000x reference)
#include <cuda_runtime.h>
#include <cstdint>
#include <math.h>

#define NB 64
#define LOOKBACK 32
#define NS 256
#define DM 512
#define DK 128
#define DV 128
#define WPC 8                   // warps per CTA in main
#define WST 4                   // stocks per warp
#define SPC (WPC * WST)         // 32 stocks per CTA
#define CPB (NS / SPC)          // 8 CTAs per batch
#define NPART CPB

// dynamic smem layout (bytes)
#define OFF_SE     0            // float4 se[32*128]        65536
#define OFF_SRED   65536        // float4 sred[128]          2048
#define OFF_SMETA  67584        // float4 smeta[32]           512
#define OFF_SW     68096        // float  sw[32]              128
#define OFF_SL     68224        // float  sl[8]                32
#define OFF_SLAST  68256        // unsigned int                4
#define SMEM_MAIN  68352

// ---- scratch (device globals: allocation-free) ----
__device__ float  g_upart[NB * 4 * DM];     // 4 partial u slices per batch
__device__ float4 g_stock[NS];              // {alpha, gate, lag_floor, lag_ceil}
__device__ float  g_pctx[NB * NPART * DM];  // CTA partial contexts (unnormalized)
__device__ float  g_l[NB * NPART];          // CTA partial exp-sums
__device__ unsigned int g_cnt[NB];          // arrival counters (zeroed in prep)

__device__ __forceinline__ float sigmoidf_(float x) {
    return 1.0f / (1.0f + __expf(-x));
}

// ============================================================================
// Kernel 1: prep. grid (4, NB) x 256 threads. CTA (g, b) computes
// q[b, g*32 .. g*32+32) and the partial u from those 32 k's into g_upart.
// ============================================================================
__global__ __launch_bounds__(256) void prep_kernel(
    const float* __restrict__ query,
    const float* __restrict__ Wq,
    const float* __restrict__ Wk,
    const float* __restrict__ lags,
    const float* __restrict__ gates,
    const void*  __restrict__ mlraw)
{
    __shared__ float  qs[DM];
    __shared__ float  qks[32];
    __shared__ float4 sred[2][DM / 4];

    const int tid = threadIdx.x;    // 0..255
    const int g   = blockIdx.x;     // 0..3 k-slice
    const int b   = blockIdx.y;     // batch

    if (g == 0 && tid == 0) g_cnt[b] = 0u;

    // per-stock meta (one CTA)
    if (g == 0 && b == 0) {
        float ml = 16.0f;
        if (mlraw != nullptr) {
            int   iv = ((const int*)mlraw)[0];
            float fv = ((const float*)mlraw)[0];
            ml = (iv > 0 && iv <= 65536) ? (float)iv : fv;
        }
        float lag = sigmoidf_(lags[tid]) * ml;
        int ifl = min(max((int)floorf(lag), 0), LOOKBACK - 1);
        int icl = min(max((int)ceilf(lag),  0), LOOKBACK - 1);
        float alpha = lag - (float)ifl;
        float gate  = sigmoidf_(gates[tid]);
        g_stock[tid] = make_float4(alpha, gate, (float)ifl, (float)icl);
    }

    qs[tid]       = query[(size_t)b * DM + tid];
    qs[tid + 256] = query[(size_t)b * DM + tid + 256];
    __syncthreads();

    // ---- stage A: q[k] for this CTA's 32-slice (warp-per-k, 4 rounds) ----
    const int wid  = tid >> 5;     // 0..7
    const int lane = tid & 31;
    #pragma unroll
    for (int r = 0; r < 4; r++) {
        const int kl = r * 8 + wid;
        const int k  = g * 32 + kl;
        float acc = 0.f;
        #pragma unroll
        for (int i = 0; i < 16; i++)
            acc = fmaf(Wq[(size_t)k * DM + i * 32 + lane], qs[i * 32 + lane], acc);
        #pragma unroll
        for (int off = 16; off; off >>= 1)
            acc += __shfl_xor_sync(0xffffffffu, acc, off);
        if (lane == 0) qks[kl] = acc;
    }
    __syncthreads();

    // ---- stage B: partial u over this CTA's 32 k's, K split 2 ways ----
    const int col  = tid & 127;    // float4 column
    const int half = tid >> 7;     // 0..1
    float4 acc = make_float4(0.f, 0.f, 0.f, 0.f);
    const float4* wkb = (const float4*)Wk + (size_t)(g * 32 + half * 16) * (DM / 4) + col;
    #pragma unroll
    for (int kk = 0; kk < 16; kk++) {
        const float  s = qks[half * 16 + kk];
        const float4 w = wkb[(size_t)kk * (DM / 4)];
        acc.x = fmaf(s, w.x, acc.x); acc.y = fmaf(s, w.y, acc.y);
        acc.z = fmaf(s, w.z, acc.z); acc.w = fmaf(s, w.w, acc.w);
    }
    sred[half][col] = acc;
    __syncthreads();

    if (tid < 128) {
        const float inv = 0.08838834764831845f;  // 1/sqrt(128)
        const float4 a = sred[0][tid], c = sred[1][tid];
        float4 r;
        r.x = (a.x + c.x) * inv; r.y = (a.y + c.y) * inv;
        r.z = (a.z + c.z) * inv; r.w = (a.w + c.w) * inv;
        ((float4*)g_upart)[((size_t)b * 4 + g) * (DM / 4) + tid] = r;
    }
}

// ============================================================================
// Kernel 2: main. Phase 1 = R8's flat 32-LDG streaming block per warp, but
// stages interpolated rows into smem (no ctx registers). Phase 2 = smem-only
// weighted accumulation straight to the CTA context. No-max softmax.
// grid (CPB, NB) x 256 threads, 68 KB dynamic smem, 3 CTAs/SM. Fused finish.
// ============================================================================
__global__ __launch_bounds__(256, 3) void main_kernel(
    const float* __restrict__ embs,
    const float* __restrict__ Wv,
    float*       __restrict__ out)
{
    extern __shared__ char smem_raw[];
    float4* se    = (float4*)(smem_raw + OFF_SE);     // [32][128] interpolated rows
    float4* sred  = (float4*)(smem_raw + OFF_SRED);   // [128] pair-reduce scratch
    float4* smeta = (float4*)(smem_raw + OFF_SMETA);  // [32] stock metas
    float*  sw    = (float*) (smem_raw + OFF_SW);     // [32] exp weights
    float*  sl    = (float*) (smem_raw + OFF_SL);     // [8] per-warp exp sums
    unsigned int* slast = (unsigned int*)(smem_raw + OFF_SLAST);

    const int tid  = threadIdx.x;
    const int lane = tid & 31;
    const int wid  = tid >> 5;        // 0..7
    const int b    = blockIdx.y;
    const int sp   = blockIdx.x;
    const int sc0  = sp * SPC;        // CTA's first stock
    const int s0   = sc0 + wid * WST; // warp's first stock

    const float4* base = (const float4*)embs + (size_t)b * LOOKBACK * NS * (DM / 4);

    if (tid < SPC) smeta[tid] = g_stock[sc0 + tid];

    // u[b] = sum of 4 partial slices (16 regs)
    const float4* up = (const float4*)g_upart + (size_t)b * 4 * (DM / 4);
    float4 u0, u1, u2, u3;
    {
        float4 t0 = up[lane],       t1 = up[128 + lane];
        float4 t2 = up[256 + lane], t3 = up[384 + lane];
        u0 = make_float4(t0.x+t1.x+t2.x+t3.x, t0.y+t1.y+t2.y+t3.y,
                         t0.z+t1.z+t2.z+t3.z, t0.w+t1.w+t2.w+t3.w);
        t0 = up[32+lane]; t1 = up[160+lane]; t2 = up[288+lane]; t3 = up[416+lane];
        u1 = make_float4(t0.x+t1.x+t2.x+t3.x, t0.y+t1.y+t2.y+t3.y,
                         t0.z+t1.z+t2.z+t3.z, t0.w+t1.w+t2.w+t3.w);
        t0 = up[64+lane]; t1 = up[192+lane]; t2 = up[320+lane]; t3 = up[448+lane];
        u2 = make_float4(t0.x+t1.x+t2.x+t3.x, t0.y+t1.y+t2.y+t3.y,
                         t0.z+t1.z+t2.z+t3.z, t0.w+t1.w+t2.w+t3.w);
        t0 = up[96+lane]; t1 = up[224+lane]; t2 = up[352+lane]; t3 = up[480+lane];
        u3 = make_float4(t0.x+t1.x+t2.x+t3.x, t0.y+t1.y+t2.y+t3.y,
                         t0.z+t1.z+t2.z+t3.z, t0.w+t1.w+t2.w+t3.w);
    }
    __syncthreads();   // smeta visible

    // ---- Phase 1: flat streaming block (R8 structure) + smem staging ----
    float p[WST];
    #pragma unroll
    for (int i = 0; i < WST; i++) {
        const int s = s0 + i;
        const float4 mt = smeta[wid * WST + i];
        const int rfo = ((int)mt.z * NS + s) * (DM / 4);
        const int rco = ((int)mt.w * NS + s) * (DM / 4);
        float4 f0 = base[rfo + lane],    f1 = base[rfo + 32 + lane];
        float4 f2 = base[rfo + 64 + lane], f3 = base[rfo + 96 + lane];
        const float4 c0 = base[rco + lane],    c1 = base[rco + 32 + lane];
        const float4 c2 = base[rco + 64 + lane], c3 = base[rco + 96 + lane];
        const float a = mt.x, oma = 1.0f - mt.x;

        f0.x = oma*f0.x + a*c0.x; f0.y = oma*f0.y + a*c0.y; f0.z = oma*f0.z + a*c0.z; f0.w = oma*f0.w + a*c0.w;
        f1.x = oma*f1.x + a*c1.x; f1.y = oma*f1.y + a*c1.y; f1.z = oma*f1.z + a*c1.z; f1.w = oma*f1.w + a*c1.w;
        f2.x = oma*f2.x + a*c2.x; f2.y = oma*f2.y + a*c2.y; f2.z = oma*f2.z + a*c2.z; f2.w = oma*f2.w + a*c2.w;
        f3.x = oma*f3.x + a*c3.x; f3.y = oma*f3.y + a*c3.y; f3.z = oma*f3.z + a*c3.z; f3.w = oma*f3.w + a*c3.w;

        // stage interpolated row to smem (fire-and-forget)
        float4* dst = se + (size_t)(wid * WST + i) * 128;
        dst[lane] = f0; dst[32 + lane] = f1; dst[64 + lane] = f2; dst[96 + lane] = f3;

        // lane-local dot partial
        const float q0 = f0.x*u0.x + f0.y*u0.y + f0.z*u0.z + f0.w*u0.w;
        const float q1 = f1.x*u1.x + f1.y*u1.y + f1.z*u1.z + f1.w*u1.w;
        const float q2 = f2.x*u2.x + f2.y*u2.y + f2.z*u2.z + f2.w*u2.w;
        const float q3 = f3.x*u3.x + f3.y*u3.y + f3.z*u3.z + f3.w*u3.w;
        p[i] = (q0 + q1) + (q2 + q3);
    }

    // ---- deferred interleaved butterflies ----
    #pragma unroll
    for (int off = 16; off; off >>= 1) {
        #pragma unroll
        for (int i = 0; i < WST; i++)
            p[i] += __shfl_xor_sync(0xffffffffu, p[i], off);
    }

    // ---- no-max exp weights (scores are O(1): no overflow risk) ----
    float l = 0.f;
    #pragma unroll
    for (int i = 0; i < WST; i++) {
        p[i] = __expf(p[i] * smeta[wid * WST + i].y);
        l += p[i];
    }
    if (lane == 0) {
        sl[wid] = l;
        #pragma unroll
        for (int i = 0; i < WST; i++) sw[wid * WST + i] = p[i];
    }
    __syncthreads();   // se + sw + sl visible to all

    // ---- Phase 2: smem-only weighted accumulation to CTA context ----
    // thread = (col, half): col 0..127, half sums 16 stocks.
    const int col = tid & 127;
    const int hh  = tid >> 7;
    float4 acc = make_float4(0.f, 0.f, 0.f, 0.f);
    {
        const float4* sb = se + (size_t)(hh * 16) * 128 + col;
        const float*  wb = sw + hh * 16;
        #pragma unroll
        for (int k = 0; k < 16; k++) {
            const float  w = wb[k];
            const float4 v = sb[(size_t)k * 128];
            acc.x += w * v.x; acc.y += w * v.y;
            acc.z += w * v.z; acc.w += w * v.w;
        }
    }
    if (hh == 1) sred[col] = acc;
    __syncthreads();

    const int idx = b * NPART + sp;
    if (hh == 0) {
        const float4 o = sred[col];
        acc.x += o.x; acc.y += o.y; acc.z += o.z; acc.w += o.w;
        ((float4*)g_pctx)[(size_t)idx * (DM / 4) + col] = acc;
        if (col == 0) {
            float L = 0.f;
            #pragma unroll
            for (int i = 0; i < WPC; i++) L += sl[i];
            g_l[idx] = L;
        }
    }

    // ---- fused finish: last CTA of batch b sums partials + applies W_v ----
    __threadfence();
    __syncthreads();
    if (tid == 0) *slast = atomicAdd(&g_cnt[b], 1u);
    __syncthreads();
    if (*slast == NPART - 1) {
        if (tid < 128) {
            float L = 0.f;
            #pragma unroll
            for (int i = 0; i < NPART; i++) L += g_l[b * NPART + i];
            const float invL = 1.0f / L;

            float4 a2 = make_float4(0.f, 0.f, 0.f, 0.f);
            const float4* pc = (const float4*)g_pctx + (size_t)b * NPART * (DM / 4) + tid;
            #pragma unroll
            for (int i = 0; i < NPART; i++) {
                const float4 v = pc[(size_t)i * (DM / 4)];
                a2.x += v.x; a2.y += v.y; a2.z += v.z; a2.w += v.w;
            }
            a2.x *= invL; a2.y *= invL; a2.z *= invL; a2.w *= invL;
            se[tid] = a2;             // ctx_emb slice (cols 0..127)
        }
        __syncthreads();

        // context[b, v] = sum_d ctx_emb[d] * Wv[v, d]
        float s0a = 0.f, s1a = 0.f;
        const float4* wv = (const float4*)Wv + (size_t)col * (DM / 4) + hh * 64;
        const float4* cx = se + hh * 64;
        #pragma unroll 8
        for (int d = 0; d < 64; d += 2) {
            const float4 wa = wv[d],     ca = cx[d];
            const float4 wb = wv[d + 1], cb = cx[d + 1];
            s0a += wa.x*ca.x + wa.y*ca.y + wa.z*ca.z + wa.w*ca.w;
            s1a += wb.x*cb.x + wb.y*cb.y + wb.z*cb.z + wb.w*cb.w;
        }
        const float part = s0a + s1a;
        __syncthreads();
        float* red = (float*)sred;
        if (hh == 1) red[col] = part;
        __syncthreads();
        if (hh == 0) out[(size_t)b * DV + col] = part + red[col];
    }
}

// ============================================================================
extern "C" void kernel_launch(void* const* d_in, const int* in_sizes, int n_in,
                              void* d_out, int out_size)
{
    const float* query = (const float*)d_in[0];   // [64, 512]
    const float* embs  = (const float*)d_in[1];   // [64, 32, 256, 512]
    const float* Wq    = (const float*)d_in[2];   // [128, 512]
    const float* Wk    = (const float*)d_in[3];   // [128, 512]
    const float* Wv    = (const float*)d_in[4];   // [128, 512]
    const float* lags  = (const float*)d_in[5];   // [256]
    const float* gates = (const float*)d_in[6];   // [256]
    const void*  ml    = (n_in > 7) ? d_in[7] : nullptr;

    cudaFuncSetAttribute(main_kernel,
                         cudaFuncAttributeMaxDynamicSharedMemorySize, SMEM_MAIN);

    prep_kernel<<<dim3(4, NB), 256>>>(query, Wq, Wk, lags, gates, ml);
    main_kernel<<<dim3(CPB, NB), 256, SMEM_MAIN>>>(embs, Wv, (float*)d_out);
}

// round 12
// speedup vs baseline: 1.3400x; 1.3400x over previous
#include <cuda_runtime.h>
#include <cstdint>
#include <math.h>

#define NB 64
#define LOOKBACK 32
#define NS 256
#define DM 512
#define DK 128
#define DV 128
#define WPC 8                   // warps per CTA in main
#define WST 4                   // stocks per warp
#define CPB (NS / (WPC * WST))  // 8 CTAs per batch
#define NPART CPB

// ---- scratch (device globals: allocation-free) ----
__device__ float  g_upart[NB * 4 * DM];     // 4 partial u slices per batch
__device__ float4 g_stock[NS];              // {alpha, gate, lag_floor, lag_ceil}
__device__ float  g_pctx[NB * NPART * DM];  // CTA partial contexts (unnormalized)
__device__ float  g_l[NB * NPART];          // CTA partial exp-sums
__device__ unsigned int g_cnt[NB];          // arrival counters (zeroed in prep)

__device__ __forceinline__ float sigmoidf_(float x) {
    return 1.0f / (1.0f + __expf(-x));
}

// ============================================================================
// Kernel 1: prep. grid (4, NB) x 256 threads. CTA (g, b) computes
// q[b, g*32 .. g*32+32) and the partial u from those 32 k's into g_upart.
// ============================================================================
__global__ __launch_bounds__(256) void prep_kernel(
    const float* __restrict__ query,
    const float* __restrict__ Wq,
    const float* __restrict__ Wk,
    const float* __restrict__ lags,
    const float* __restrict__ gates,
    const void*  __restrict__ mlraw)
{
    __shared__ float  qs[DM];
    __shared__ float  qks[32];
    __shared__ float4 sred[2][DM / 4];

    const int tid = threadIdx.x;    // 0..255
    const int g   = blockIdx.x;     // 0..3 k-slice
    const int b   = blockIdx.y;     // batch

    if (g == 0 && tid == 0) g_cnt[b] = 0u;

    // per-stock meta (one CTA)
    if (g == 0 && b == 0) {
        float ml = 16.0f;
        if (mlraw != nullptr) {
            int   iv = ((const int*)mlraw)[0];
            float fv = ((const float*)mlraw)[0];
            ml = (iv > 0 && iv <= 65536) ? (float)iv : fv;
        }
        float lag = sigmoidf_(lags[tid]) * ml;
        int ifl = min(max((int)floorf(lag), 0), LOOKBACK - 1);
        int icl = min(max((int)ceilf(lag),  0), LOOKBACK - 1);
        float alpha = lag - (float)ifl;
        float gate  = sigmoidf_(gates[tid]);
        g_stock[tid] = make_float4(alpha, gate, (float)ifl, (float)icl);
    }

    qs[tid]       = query[(size_t)b * DM + tid];
    qs[tid + 256] = query[(size_t)b * DM + tid + 256];
    __syncthreads();

    // ---- stage A: q[k] for this CTA's 32-slice (warp-per-k, 4 rounds) ----
    const int wid  = tid >> 5;     // 0..7
    const int lane = tid & 31;
    #pragma unroll
    for (int r = 0; r < 4; r++) {
        const int kl = r * 8 + wid;
        const int k  = g * 32 + kl;
        float acc = 0.f;
        #pragma unroll
        for (int i = 0; i < 16; i++)
            acc = fmaf(Wq[(size_t)k * DM + i * 32 + lane], qs[i * 32 + lane], acc);
        #pragma unroll
        for (int off = 16; off; off >>= 1)
            acc += __shfl_xor_sync(0xffffffffu, acc, off);
        if (lane == 0) qks[kl] = acc;
    }
    __syncthreads();

    // ---- stage B: partial u over this CTA's 32 k's, K split 2 ways ----
    const int col  = tid & 127;    // float4 column
    const int half = tid >> 7;     // 0..1
    float4 acc = make_float4(0.f, 0.f, 0.f, 0.f);
    const float4* wkb = (const float4*)Wk + (size_t)(g * 32 + half * 16) * (DM / 4) + col;
    #pragma unroll
    for (int kk = 0; kk < 16; kk++) {
        const float  s = qks[half * 16 + kk];
        const float4 w = wkb[(size_t)kk * (DM / 4)];
        acc.x = fmaf(s, w.x, acc.x); acc.y = fmaf(s, w.y, acc.y);
        acc.z = fmaf(s, w.z, acc.z); acc.w = fmaf(s, w.w, acc.w);
    }
    sred[half][col] = acc;
    __syncthreads();

    if (tid < 128) {
        const float inv = 0.08838834764831845f;  // 1/sqrt(128)
        const float4 a = sred[0][tid], c = sred[1][tid];
        float4 r;
        r.x = (a.x + c.x) * inv; r.y = (a.y + c.y) * inv;
        r.z = (a.z + c.z) * inv; r.w = (a.w + c.w) * inv;
        ((float4*)g_upart)[((size_t)b * 4 + g) * (DM / 4) + tid] = r;
    }
}

// ============================================================================
// Kernel 2: main. R8 two-phase structure with: hoisted meta/addresses,
// explicit 2-stock load grouping (16 concurrent LDG.128 per burst), and
// no-max softmax (plain-sum combines). grid (CPB, NB) x 256 thr. Fused finish.
// ============================================================================
__global__ __launch_bounds__(256, 2) void main_kernel(
    const float* __restrict__ embs,
    const float* __restrict__ Wv,
    float*       __restrict__ out)
{
    __shared__ float4 sctx[WPC * (DM / 4)];   // 16 KB combine scratch
    __shared__ float  sl[WPC];
    __shared__ unsigned int slast;

    const int tid  = threadIdx.x;
    const int lane = tid & 31;
    const int wid  = tid >> 5;        // 0..7
    const int b    = blockIdx.y;
    const int sp   = blockIdx.x;
    const int s0   = (sp * WPC + wid) * WST;

    const float4* __restrict__ base =
        (const float4*)embs + (size_t)b * LOOKBACK * NS * (DM / 4);

    // ---- hoist meta + row offsets (kills per-iteration address dependency) ----
    float alpha_[WST], gate_[WST];
    int   rfo[WST], rco[WST];
    #pragma unroll
    for (int i = 0; i < WST; i++) {
        const float4 mt = g_stock[s0 + i];
        alpha_[i] = mt.x; gate_[i] = mt.y;
        rfo[i] = ((int)mt.z * NS + s0 + i) * (DM / 4);
        rco[i] = ((int)mt.w * NS + s0 + i) * (DM / 4);
    }

    // u[b] = sum of 4 partial slices (16 regs)
    const float4* up = (const float4*)g_upart + (size_t)b * 4 * (DM / 4);
    float4 u0, u1, u2, u3;
    {
        float4 t0 = up[lane],       t1 = up[128 + lane];
        float4 t2 = up[256 + lane], t3 = up[384 + lane];
        u0 = make_float4(t0.x+t1.x+t2.x+t3.x, t0.y+t1.y+t2.y+t3.y,
                         t0.z+t1.z+t2.z+t3.z, t0.w+t1.w+t2.w+t3.w);
        t0 = up[32+lane]; t1 = up[160+lane]; t2 = up[288+lane]; t3 = up[416+lane];
        u1 = make_float4(t0.x+t1.x+t2.x+t3.x, t0.y+t1.y+t2.y+t3.y,
                         t0.z+t1.z+t2.z+t3.z, t0.w+t1.w+t2.w+t3.w);
        t0 = up[64+lane]; t1 = up[192+lane]; t2 = up[320+lane]; t3 = up[448+lane];
        u2 = make_float4(t0.x+t1.x+t2.x+t3.x, t0.y+t1.y+t2.y+t3.y,
                         t0.z+t1.z+t2.z+t3.z, t0.w+t1.w+t2.w+t3.w);
        t0 = up[96+lane]; t1 = up[224+lane]; t2 = up[352+lane]; t3 = up[480+lane];
        u3 = make_float4(t0.x+t1.x+t2.x+t3.x, t0.y+t1.y+t2.y+t3.y,
                         t0.z+t1.z+t2.z+t3.z, t0.w+t1.w+t2.w+t3.w);
    }

    // ---- Phase 1: lane-local dots, 2-stock load groups (16 LDG bursts) ----
    float p[WST];
    #pragma unroll
    for (int j = 0; j < WST; j += 2) {
        // burst: all 16 loads of stocks j and j+1
        const float4 af0 = base[rfo[j] + lane],      af1 = base[rfo[j] + 32 + lane];
        const float4 af2 = base[rfo[j] + 64 + lane], af3 = base[rfo[j] + 96 + lane];
        const float4 ac0 = base[rco[j] + lane],      ac1 = base[rco[j] + 32 + lane];
        const float4 ac2 = base[rco[j] + 64 + lane], ac3 = base[rco[j] + 96 + lane];
        const float4 bf0 = base[rfo[j+1] + lane],      bf1 = base[rfo[j+1] + 32 + lane];
        const float4 bf2 = base[rfo[j+1] + 64 + lane], bf3 = base[rfo[j+1] + 96 + lane];
        const float4 bc0 = base[rco[j+1] + lane],      bc1 = base[rco[j+1] + 32 + lane];
        const float4 bc2 = base[rco[j+1] + 64 + lane], bc3 = base[rco[j+1] + 96 + lane];

        const float aa = alpha_[j],   aoma = 1.0f - aa;
        const float ba = alpha_[j+1], boma = 1.0f - ba;

        float qa =
            (aoma*af0.x + aa*ac0.x)*u0.x + (aoma*af0.y + aa*ac0.y)*u0.y +
            (aoma*af0.z + aa*ac0.z)*u0.z + (aoma*af0.w + aa*ac0.w)*u0.w +
            (aoma*af1.x + aa*ac1.x)*u1.x + (aoma*af1.y + aa*ac1.y)*u1.y +
            (aoma*af1.z + aa*ac1.z)*u1.z + (aoma*af1.w + aa*ac1.w)*u1.w +
            (aoma*af2.x + aa*ac2.x)*u2.x + (aoma*af2.y + aa*ac2.y)*u2.y +
            (aoma*af2.z + aa*ac2.z)*u2.z + (aoma*af2.w + aa*ac2.w)*u2.w +
            (aoma*af3.x + aa*ac3.x)*u3.x + (aoma*af3.y + aa*ac3.y)*u3.y +
            (aoma*af3.z + aa*ac3.z)*u3.z + (aoma*af3.w + aa*ac3.w)*u3.w;
        float qb =
            (boma*bf0.x + ba*bc0.x)*u0.x + (boma*bf0.y + ba*bc0.y)*u0.y +
            (boma*bf0.z + ba*bc0.z)*u0.z + (boma*bf0.w + ba*bc0.w)*u0.w +
            (boma*bf1.x + ba*bc1.x)*u1.x + (boma*bf1.y + ba*bc1.y)*u1.y +
            (boma*bf1.z + ba*bc1.z)*u1.z + (boma*bf1.w + ba*bc1.w)*u1.w +
            (boma*bf2.x + ba*bc2.x)*u2.x + (boma*bf2.y + ba*bc2.y)*u2.y +
            (boma*bf2.z + ba*bc2.z)*u2.z + (boma*bf2.w + ba*bc2.w)*u2.w +
            (boma*bf3.x + ba*bc3.x)*u3.x + (boma*bf3.y + ba*bc3.y)*u3.y +
            (boma*bf3.z + ba*bc3.z)*u3.z + (boma*bf3.w + ba*bc3.w)*u3.w;
        p[j]     = qa;
        p[j + 1] = qb;
    }

    // ---- interleaved butterfly reductions ----
    #pragma unroll
    for (int off = 16; off; off >>= 1) {
        #pragma unroll
        for (int i = 0; i < WST; i++)
            p[i] += __shfl_xor_sync(0xffffffffu, p[i], off);
    }

    // ---- no-max exp weights (scores O(1): no overflow) ----
    float l = 0.f;
    #pragma unroll
    for (int i = 0; i < WST; i++) {
        p[i] = __expf(p[i] * gate_[i]);
        l += p[i];
    }

    // ---- Phase 2: re-stream (L2-resident), 2-stock groups, weighted ctx ----
    float4 x0 = make_float4(0.f,0.f,0.f,0.f), x1 = x0, x2 = x0, x3 = x0;
    #pragma unroll
    for (int j = 0; j < WST; j += 2) {
        const float4 af0 = base[rfo[j] + lane],      af1 = base[rfo[j] + 32 + lane];
        const float4 af2 = base[rfo[j] + 64 + lane], af3 = base[rfo[j] + 96 + lane];
        const float4 ac0 = base[rco[j] + lane],      ac1 = base[rco[j] + 32 + lane];
        const float4 ac2 = base[rco[j] + 64 + lane], ac3 = base[rco[j] + 96 + lane];
        const float4 bf0 = base[rfo[j+1] + lane],      bf1 = base[rfo[j+1] + 32 + lane];
        const float4 bf2 = base[rfo[j+1] + 64 + lane], bf3 = base[rfo[j+1] + 96 + lane];
        const float4 bc0 = base[rco[j+1] + lane],      bc1 = base[rco[j+1] + 32 + lane];
        const float4 bc2 = base[rco[j+1] + 64 + lane], bc3 = base[rco[j+1] + 96 + lane];

        const float aa = alpha_[j],   aoma = 1.0f - aa;
        const float ba = alpha_[j+1], boma = 1.0f - ba;
        const float wa = p[j], wb = p[j+1];

        x0.x += wa*(aoma*af0.x + aa*ac0.x) + wb*(boma*bf0.x + ba*bc0.x);
        x0.y += wa*(aoma*af0.y + aa*ac0.y) + wb*(boma*bf0.y + ba*bc0.y);
        x0.z += wa*(aoma*af0.z + aa*ac0.z) + wb*(boma*bf0.z + ba*bc0.z);
        x0.w += wa*(aoma*af0.w + aa*ac0.w) + wb*(boma*bf0.w + ba*bc0.w);
        x1.x += wa*(aoma*af1.x + aa*ac1.x) + wb*(boma*bf1.x + ba*bc1.x);
        x1.y += wa*(aoma*af1.y + aa*ac1.y) + wb*(boma*bf1.y + ba*bc1.y);
        x1.z += wa*(aoma*af1.z + aa*ac1.z) + wb*(boma*bf1.z + ba*bc1.z);
        x1.w += wa*(aoma*af1.w + aa*ac1.w) + wb*(boma*bf1.w + ba*bc1.w);
        x2.x += wa*(aoma*af2.x + aa*ac2.x) + wb*(boma*bf2.x + ba*bc2.x);
        x2.y += wa*(aoma*af2.y + aa*ac2.y) + wb*(boma*bf2.y + ba*bc2.y);
        x2.z += wa*(aoma*af2.z + aa*ac2.z) + wb*(boma*bf2.z + ba*bc2.z);
        x2.w += wa*(aoma*af2.w + aa*ac2.w) + wb*(boma*bf2.w + ba*bc2.w);
        x3.x += wa*(aoma*af3.x + aa*ac3.x) + wb*(boma*bf3.x + ba*bc3.x);
        x3.y += wa*(aoma*af3.y + aa*ac3.y) + wb*(boma*bf3.y + ba*bc3.y);
        x3.z += wa*(aoma*af3.z + aa*ac3.z) + wb*(boma*bf3.z + ba*bc3.z);
        x3.w += wa*(aoma*af3.w + aa*ac3.w) + wb*(boma*bf3.w + ba*bc3.w);
    }

    // ---- CTA combine: plain sums ----
    if (lane == 0) sl[wid] = l;
    sctx[wid * 128 + lane]      = x0;
    sctx[wid * 128 + 32 + lane] = x1;
    sctx[wid * 128 + 64 + lane] = x2;
    sctx[wid * 128 + 96 + lane] = x3;
    __syncthreads();

    const int idx = b * NPART + sp;
    if (tid < 128) {
        if (tid == 0) {
            float L = 0.f;
            #pragma unroll
            for (int i = 0; i < WPC; i++) L += sl[i];
            g_l[idx] = L;
        }
        float4 comb = make_float4(0.f, 0.f, 0.f, 0.f);
        #pragma unroll
        for (int i = 0; i < WPC; i++) {
            const float4 v = sctx[i * 128 + tid];
            comb.x += v.x; comb.y += v.y; comb.z += v.z; comb.w += v.w;
        }
        ((float4*)g_pctx)[(size_t)idx * (DM / 4) + tid] = comb;
    }

    // ---- fused finish: last CTA of batch b sums partials + applies W_v ----
    __threadfence();
    __syncthreads();
    if (tid == 0) slast = atomicAdd(&g_cnt[b], 1u);
    __syncthreads();
    if (slast == NPART - 1) {
        if (tid < 128) {
            float L = 0.f;
            #pragma unroll
            for (int i = 0; i < NPART; i++) L += g_l[b * NPART + i];
            const float invL = 1.0f / L;

            float4 a2 = make_float4(0.f, 0.f, 0.f, 0.f);
            const float4* pc = (const float4*)g_pctx + (size_t)b * NPART * (DM / 4) + tid;
            #pragma unroll
            for (int i = 0; i < NPART; i++) {
                const float4 v = pc[(size_t)i * (DM / 4)];
                a2.x += v.x; a2.y += v.y; a2.z += v.z; a2.w += v.w;
            }
            a2.x *= invL; a2.y *= invL; a2.z *= invL; a2.w *= invL;
            sctx[tid] = a2;             // ctx_emb slice (cols 0..127)
        }
        __syncthreads();

        // context[b, v] = sum_d ctx_emb[d] * Wv[v, d]
        const int v  = tid & 127;
        const int hh = tid >> 7;
        float s0a = 0.f, s1a = 0.f;
        const float4* wv = (const float4*)Wv + (size_t)v * (DM / 4) + hh * 64;
        const float4* cx = sctx + hh * 64;
        #pragma unroll 8
        for (int d = 0; d < 64; d += 2) {
            const float4 wa = wv[d],     ca = cx[d];
            const float4 wb = wv[d + 1], cb = cx[d + 1];
            s0a += wa.x*ca.x + wa.y*ca.y + wa.z*ca.z + wa.w*ca.w;
            s1a += wb.x*cb.x + wb.y*cb.y + wb.z*cb.z + wb.w*cb.w;
        }
        const float part = s0a + s1a;
        __syncthreads();
        float* red = (float*)(sctx + 256);
        if (hh == 1) red[v] = part;
        __syncthreads();
        if (hh == 0) out[(size_t)b * DV + v] = part + red[v];
    }
}

// ============================================================================
extern "C" void kernel_launch(void* const* d_in, const int* in_sizes, int n_in,
                              void* d_out, int out_size)
{
    const float* query = (const float*)d_in[0];   // [64, 512]
    const float* embs  = (const float*)d_in[1];   // [64, 32, 256, 512]
    const float* Wq    = (const float*)d_in[2];   // [128, 512]
    const float* Wk    = (const float*)d_in[3];   // [128, 512]
    const float* Wv    = (const float*)d_in[4];   // [128, 512]
    const float* lags  = (const float*)d_in[5];   // [256]
    const float* gates = (const float*)d_in[6];   // [256]
    const void*  ml    = (n_in > 7) ? d_in[7] : nullptr;

    prep_kernel<<<dim3(4, NB), 256>>>(query, Wq, Wk, lags, gates, ml);
    main_kernel<<<dim3(CPB, NB), 256>>>(embs, Wv, (float*)d_out);
}